// round 13
// baseline (speedup 1.0000x reference)
#include <cuda_runtime.h>

// MeshHandler: gather -> MLP(6->8->8->8->3, sigmoid) -> scatter-add.
// Converged model: mesh kernel sits ~5% above the L1TEX/LSU lane-op floor
// (12M divergent gathers @ ~1 cyc/wf + 12M spread REDs @ 1.29 cyc/lane
//  ~= 186K cyc/SM ~= 91us). Parallelism levers proven neutral (R6/R10/R11).
// R13: finer CTA granularity — block 128, 10 CTAs/SM (same threads/SM) to
// reduce cross-CTA L1tex-queue spread + tail-wave quantization slack.

#define NW 227  // packed weight count: 48+8 + 64+8 + 64+8 + 24+3

__device__ unsigned long long g_w[NW];      // staging (written by prep kernel)
__constant__ unsigned long long c_w[NW];    // hot copy (const port)
__device__ int g_adj_i32;   // 1 if adjacency is int32, 0 if int64

static __device__ __forceinline__ unsigned long long pack2(float lo, float hi) {
    unsigned long long r;
    asm("mov.b64 %0, {%1, %2};" : "=l"(r) : "f"(lo), "f"(hi));
    return r;
}
static __device__ __forceinline__ void unpack2(unsigned long long v, float& lo, float& hi) {
    asm("mov.b64 {%0, %1}, %2;" : "=f"(lo), "=f"(hi) : "l"(v));
}
static __device__ __forceinline__ unsigned long long fma2(unsigned long long a,
                                                          unsigned long long b,
                                                          unsigned long long c) {
    unsigned long long d;
    asm("fma.rn.f32x2 %0, %1, %2, %3;" : "=l"(d) : "l"(a), "l"(b), "l"(c));
    return d;
}
static __device__ __forceinline__ float tanh_approx(float x) {
    float y;
    asm("tanh.approx.f32 %0, %1;" : "=f"(y) : "f"(x));
    return y;
}
static __device__ __forceinline__ unsigned long long tanh2(unsigned long long v) {
    float lo, hi;
    unpack2(v, lo, hi);
    return pack2(tanh_approx(lo), tanh_approx(hi));
}

// ---------------------------------------------------------------------------
// Prep + zero: block 0 folds sigmoid(z)=0.5*tanh(0.5z)+0.5 into pre-scaled
// weights and sniffs the adjacency dtype; ALL blocks zero a stripe of d_out.
// Weight layout: A1[6][8]@0, c1[8]@48, A2[8][8]@56, c2[8]@120,
//                A3[8][8]@128, c3[8]@192, A4[8][3]@200, c4[3]@224.
// ---------------------------------------------------------------------------
__global__ void prep_zero_kernel(const void* __restrict__ adj_raw,
                                 const float* __restrict__ W1, const float* __restrict__ b1,
                                 const float* __restrict__ W2, const float* __restrict__ b2,
                                 const float* __restrict__ W3, const float* __restrict__ b3,
                                 const float* __restrict__ W4, const float* __restrict__ b4,
                                 float* __restrict__ out, int out_n) {
    // --- all blocks: zero a stripe of out (vectorized where possible) ---
    int tid = blockIdx.x * blockDim.x + threadIdx.x;
    int n4 = out_n >> 2;
    float4* out4 = reinterpret_cast<float4*>(out);
    int stride = gridDim.x * blockDim.x;
    for (int i = tid; i < n4; i += stride)
        out4[i] = make_float4(0.f, 0.f, 0.f, 0.f);
    for (int i = 4 * n4 + tid; i < out_n; i += stride)
        out[i] = 0.f;

    // --- block 0: dtype sniff + weight fold ---
    if (blockIdx.x != 0) return;
    int t = threadIdx.x;
    if (t == 0) {
        const unsigned int* raw = (const unsigned int*)adj_raw;
        unsigned int orr = 0;
        #pragma unroll 8
        for (int i = 0; i < 64; i++) orr |= raw[2 * i + 1];
        g_adj_i32 = (orr != 0u) ? 1 : 0;
    }
    float v;
    if (t < 48) {
        v = 0.5f * W1[t];
    } else if (t < 56) {
        v = 0.5f * b1[t - 48];
    } else if (t < 120) {
        v = 0.25f * W2[t - 56];
    } else if (t < 128) {
        int j = t - 120;
        float s = 0.f;
        for (int i = 0; i < 8; i++) s += W2[i * 8 + j];
        v = 0.25f * s + 0.5f * b2[j];
    } else if (t < 192) {
        v = 0.25f * W3[t - 128];
    } else if (t < 200) {
        int j = t - 192;
        float s = 0.f;
        for (int i = 0; i < 8; i++) s += W3[i * 8 + j];
        v = 0.25f * s + 0.5f * b3[j];
    } else if (t < 224) {
        v = 0.25f * W4[t - 200];
    } else if (t < NW) {
        int j = t - 224;
        float s = 0.f;
        for (int i = 0; i < 8; i++) s += W4[i * 3 + j];
        v = 0.25f * s + 0.5f * b4[j];
    } else {
        return;
    }
    g_w[t] = pack2(v, v);
}

// ---------------------------------------------------------------------------
// Main: one thread = 2 elements (fp32x2 lanes lo/hi). Weights via const port.
// Block 128, up to 10 CTAs/SM.
// ---------------------------------------------------------------------------
__global__ __launch_bounds__(128, 10) void mesh_kernel(const float2* __restrict__ points,
                                                       const void* __restrict__ adj_raw,
                                                       float* __restrict__ out,
                                                       int nelems) {
    int p = blockIdx.x * 128 + threadIdx.x;
    int npairs = (nelems + 1) >> 1;
    if (p >= npairs) return;
    bool full = (2 * p + 1 < nelems);

    // Gather the 6 vertex indices of this pair (uniform dtype branch).
    int v0, v1, v2, v3, v4, v5;
    if (g_adj_i32) {
        const int2* a2 = reinterpret_cast<const int2*>(adj_raw) + (size_t)p * 3;
        if (full) {
            int2 A = __ldg(a2);
            int2 B = __ldg(a2 + 1);
            int2 C = __ldg(a2 + 2);
            v0 = A.x; v1 = A.y; v2 = B.x;
            v3 = B.y; v4 = C.x; v5 = C.y;
        } else {
            const int* a = reinterpret_cast<const int*>(adj_raw) + (size_t)p * 6;
            v0 = a[0]; v1 = a[1]; v2 = a[2];
            v3 = v0; v4 = v1; v5 = v2;
        }
    } else {
        const longlong2* a2 = reinterpret_cast<const longlong2*>(adj_raw) + (size_t)p * 3;
        if (full) {
            longlong2 A = __ldg(a2);
            longlong2 B = __ldg(a2 + 1);
            longlong2 C = __ldg(a2 + 2);
            v0 = (int)A.x; v1 = (int)A.y; v2 = (int)B.x;
            v3 = (int)B.y; v4 = (int)C.x; v5 = (int)C.y;
        } else {
            const long long* a = reinterpret_cast<const long long*>(adj_raw) + (size_t)p * 6;
            v0 = (int)a[0]; v1 = (int)a[1]; v2 = (int)a[2];
            v3 = v0; v4 = v1; v5 = v2;
        }
    }

    float2 q0 = __ldg(points + v0);
    float2 q1 = __ldg(points + v1);
    float2 q2 = __ldg(points + v2);
    float2 q3 = __ldg(points + v3);
    float2 q4 = __ldg(points + v4);
    float2 q5 = __ldg(points + v5);

    unsigned long long x[6];
    x[0] = pack2(q0.x, q3.x);
    x[1] = pack2(q0.y, q3.y);
    x[2] = pack2(q1.x, q4.x);
    x[3] = pack2(q1.y, q4.y);
    x[4] = pack2(q2.x, q5.x);
    x[5] = pack2(q2.y, q5.y);

    unsigned long long t[8], u[8];

    // Layer 1: 6 -> 8
    #pragma unroll
    for (int j = 0; j < 8; j++) {
        unsigned long long acc = c_w[48 + j];
        #pragma unroll
        for (int i = 0; i < 6; i++) acc = fma2(x[i], c_w[i * 8 + j], acc);
        t[j] = tanh2(acc);
    }
    // Layer 2: 8 -> 8
    #pragma unroll
    for (int j = 0; j < 8; j++) {
        unsigned long long acc = c_w[120 + j];
        #pragma unroll
        for (int i = 0; i < 8; i++) acc = fma2(t[i], c_w[56 + i * 8 + j], acc);
        u[j] = tanh2(acc);
    }
    // Layer 3: 8 -> 8
    #pragma unroll
    for (int j = 0; j < 8; j++) {
        unsigned long long acc = c_w[192 + j];
        #pragma unroll
        for (int i = 0; i < 8; i++) acc = fma2(u[i], c_w[128 + i * 8 + j], acc);
        t[j] = tanh2(acc);
    }
    // Layer 4: 8 -> 3, out = 0.5*t + 0.5, scatter-add
    const unsigned long long HALF2 = 0x3F0000003F000000ULL;
    int e0v[3] = {v0, v1, v2};
    int e1v[3] = {v3, v4, v5};
    #pragma unroll
    for (int j = 0; j < 3; j++) {
        unsigned long long acc = c_w[224 + j];
        #pragma unroll
        for (int i = 0; i < 8; i++) acc = fma2(t[i], c_w[200 + i * 3 + j], acc);
        unsigned long long w = fma2(tanh2(acc), HALF2, HALF2);
        float wlo, whi;
        unpack2(w, wlo, whi);
        atomicAdd(out + e0v[j], wlo);
        if (full) atomicAdd(out + e1v[j], whi);
    }
}

extern "C" void kernel_launch(void* const* d_in, const int* in_sizes, int n_in,
                              void* d_out, int out_size) {
    const float2* points = (const float2*)d_in[0];
    const void* adj = d_in[1];

    // Fused: zero d_out (all blocks) + fold weights / sniff dtype (block 0).
    int zgrid = (out_size / 4 + 255) / 256;
    if (zgrid < 1) zgrid = 1;
    if (zgrid > 2048) zgrid = 2048;
    prep_zero_kernel<<<zgrid, 256>>>(adj,
                                     (const float*)d_in[2], (const float*)d_in[3],
                                     (const float*)d_in[4], (const float*)d_in[5],
                                     (const float*)d_in[6], (const float*)d_in[7],
                                     (const float*)d_in[8], (const float*)d_in[9],
                                     (float*)d_out, out_size);

    // Stage folded weights into the constant bank (D2D copy, capturable).
    void* g_w_addr = nullptr;
    cudaGetSymbolAddress(&g_w_addr, g_w);
    cudaMemcpyToSymbolAsync(c_w, g_w_addr, NW * sizeof(unsigned long long), 0,
                            cudaMemcpyDeviceToDevice);

    int nelems = in_sizes[1] / 3;
    int npairs = (nelems + 1) / 2;
    int grid = (npairs + 127) / 128;
    mesh_kernel<<<grid, 128>>>(points, adj, (float*)d_out, nelems);
}